// round 2
// baseline (speedup 1.0000x reference)
#include <cuda_runtime.h>
#include <cuda_bf16.h>

// RUDY congestion map via 2D difference-array + summed-area reconstruction.
//
// Each net contributes  w_h * ox(x) * oy(y)  (and w_v * ...) where ox/oy are
// bin-overlap vectors that are constant (=BSX) in the interior of the bbox and
// partial only at the 2 edge bins.  The mixed 2D difference of that separable
// contribution is the outer product of two vectors with <=4 nonzeros each
// (at {lo, lo+1, hi, hi+1}).  Scatter <=16 atomics per map per net into a
// (513x514) difference grid, then an inclusive row-scan (y) and column-scan
// (x) reconstructs the maps exactly (telescoping), and we finalize with
// max(|h|,|v|).  Scale 1/(bin_area*CAP) is folded into the per-net weights.

#define NBX 512
#define NBY 512
#define DPITCH 514          // row pitch of diff arrays (need columns 0..512)
#define DROWS  513          // need rows 0..512

__device__ float g_diffH[DROWS * DPITCH];
__device__ float g_diffV[DROWS * DPITCH];

__device__ __forceinline__ float edge(int i, float bs) {
    // bin edge i * bs ; bs = 1000/512 = 125/64 exactly representable,
    // i*bs exact in fp32 for the index range used here.
    return (float)i * bs;
}

// overlap of [vmin, vmax] with bin i, clipped to [0, bs] — identical formula
// to the reference's clip(min(vmax, e[i+1]) - max(vmin, e[i]), 0, bs).
__device__ __forceinline__ float fval(float vmin, float vmax, int i, float bs) {
    float lo_e = edge(i, bs);
    float hi_e = edge(i + 1, bs);
    float ov = fminf(vmax, hi_e) - fmaxf(vmin, lo_e);
    return fminf(fmaxf(ov, 0.0f), bs);
}

// exact bin index of v (0..nb-1), correcting fp error in the division against
// the exactly-representable edges.
__device__ __forceinline__ int bin_of(float v, float inv_bs, float bs, int nb) {
    int i = (int)(v * inv_bs);
    if (i > nb - 1) i = nb - 1;
    if (i < 0) i = 0;
    if (i > 0 && v < edge(i, bs)) --i;
    else if (i < nb - 1 && v >= edge(i + 1, bs)) ++i;
    return i;
}

__global__ void zero_diff_kernel() {
    int total = DROWS * DPITCH;
    for (int i = blockIdx.x * blockDim.x + threadIdx.x; i < total;
         i += gridDim.x * blockDim.x) {
        g_diffH[i] = 0.0f;
        g_diffV[i] = 0.0f;
    }
}

__global__ void scatter_kernel(const float* __restrict__ pin_pos,
                               const float* __restrict__ net_weights,
                               const int* __restrict__ netpin_start,
                               const int* __restrict__ flat_netpin,
                               int num_nets, int P) {
    const float BSX = 1.953125f;          // 1000/512, exact
    const float BSY = 1.953125f;
    const float INV_BSX = 1.0f / 1.953125f;
    const float INV_BSY = 1.0f / 1.953125f;
    const float SCALE = 262144.0f / 100000.0f;  // 1/(BSX*BSY*0.1)

    for (int n = blockIdx.x * blockDim.x + threadIdx.x; n < num_nets;
         n += gridDim.x * blockDim.x) {
        int s = netpin_start[n];
        int e = netpin_start[n + 1];

        float xmin = 3.0e38f, xmax = -3.0e38f, ymin = 3.0e38f, ymax = -3.0e38f;
        for (int p = s; p < e; ++p) {
            int idx = __ldg(&flat_netpin[p]);
            float x = __ldg(&pin_pos[idx]);
            float y = __ldg(&pin_pos[P + idx]);
            xmin = fminf(xmin, x); xmax = fmaxf(xmax, x);
            ymin = fminf(ymin, y); ymax = fmaxf(ymax, y);
        }

        float sx = xmax - xmin;
        float sy = ymax - ymin;
        // if either span is 0, the corresponding overlap vector is all-zero
        // and BOTH maps receive nothing from this net (ox*oy multiplies both).
        if (!(sx > 0.0f) || !(sy > 0.0f)) continue;

        float wt = net_weights[n] * SCALE;
        float wh = wt / sy;   // horizontal demand weight
        float wv = wt / sx;   // vertical demand weight

        int lox = bin_of(xmin, INV_BSX, BSX, NBX);
        int hix = bin_of(xmax, INV_BSX, BSX, NBX);
        int loy = bin_of(ymin, INV_BSY, BSY, NBY);
        int hiy = bin_of(ymax, INV_BSY, BSY, NBY);

        // unique difference positions along x: subset of {lo, lo+1, hi, hi+1}
        int pxs[4]; float dxs[4]; int mx = 0;
        pxs[mx++] = lox;
        pxs[mx++] = lox + 1;
        if (hix > lox + 1) pxs[mx++] = hix;
        if (hix + 1 > lox + 1) pxs[mx++] = hix + 1;
#pragma unroll
        for (int i = 0; i < 4; ++i) {
            if (i < mx)
                dxs[i] = fval(xmin, xmax, pxs[i], BSX)
                       - fval(xmin, xmax, pxs[i] - 1, BSX);
        }

        int pys[4]; float dys[4]; int my = 0;
        pys[my++] = loy;
        pys[my++] = loy + 1;
        if (hiy > loy + 1) pys[my++] = hiy;
        if (hiy + 1 > loy + 1) pys[my++] = hiy + 1;
#pragma unroll
        for (int j = 0; j < 4; ++j) {
            if (j < my)
                dys[j] = fval(ymin, ymax, pys[j], BSY)
                       - fval(ymin, ymax, pys[j] - 1, BSY);
        }

#pragma unroll
        for (int i = 0; i < 4; ++i) {
            if (i >= mx) break;
#pragma unroll
            for (int j = 0; j < 4; ++j) {
                if (j >= my) break;
                float v = dxs[i] * dys[j];
                int off = pxs[i] * DPITCH + pys[j];
                atomicAdd(&g_diffH[off], wh * v);
                atomicAdd(&g_diffV[off], wv * v);
            }
        }
    }
}

// inclusive scan along y (inner dim) for rows 0..511 of each diff array.
__global__ void row_scan_kernel() {
    __shared__ float warp_sums[16];
    float* D = blockIdx.y ? g_diffV : g_diffH;
    int row = blockIdx.x;
    int t = threadIdx.x;
    int lane = t & 31, wid = t >> 5;

    float v = D[row * DPITCH + t];
#pragma unroll
    for (int o = 1; o < 32; o <<= 1) {
        float nv = __shfl_up_sync(0xffffffff, v, o);
        if (lane >= o) v += nv;
    }
    if (lane == 31) warp_sums[wid] = v;
    __syncthreads();
    if (wid == 0) {
        float sv = (lane < 16) ? warp_sums[lane] : 0.0f;
#pragma unroll
        for (int o = 1; o < 16; o <<= 1) {
            float nv = __shfl_up_sync(0xffffffff, sv, o);
            if (lane >= o) sv += nv;
        }
        if (lane < 16) warp_sums[lane] = sv;
    }
    __syncthreads();
    if (wid > 0) v += warp_sums[wid - 1];
    D[row * DPITCH + t] = v;
}

// running sum down x per column + finalize max(|h|,|v|).
__global__ void col_scan_finalize_kernel(float* __restrict__ out) {
    int y = blockIdx.x * blockDim.x + threadIdx.x;
    if (y >= NBY) return;
    float ah = 0.0f, av = 0.0f;
#pragma unroll 4
    for (int x = 0; x < NBX; ++x) {
        ah += g_diffH[x * DPITCH + y];
        av += g_diffV[x * DPITCH + y];
        out[x * NBY + y] = fmaxf(fabsf(ah), fabsf(av));
    }
}

extern "C" void kernel_launch(void* const* d_in, const int* in_sizes, int n_in,
                              void* d_out, int out_size) {
    const float* pin_pos      = (const float*)d_in[0];
    const float* net_weights  = (const float*)d_in[1];
    const int*   netpin_start = (const int*)d_in[2];
    const int*   flat_netpin  = (const int*)d_in[3];
    float* out = (float*)d_out;

    int P = in_sizes[0] / 2;
    int num_nets = in_sizes[2] - 1;

    zero_diff_kernel<<<256, 256>>>();
    scatter_kernel<<<(num_nets + 127) / 128, 128>>>(
        pin_pos, net_weights, netpin_start, flat_netpin, num_nets, P);
    row_scan_kernel<<<dim3(NBX, 2), NBY>>>();
    col_scan_finalize_kernel<<<4, 128>>>(out);
}

// round 3
// speedup vs baseline: 2.1612x; 2.1612x over previous
#include <cuda_runtime.h>
#include <cuda_bf16.h>

// RUDY congestion map via 2D difference-array + summed-area reconstruction.
//
// diff grid (513x514) receives <=16 atomics per map per net (mixed 2D
// difference of the separable overlap contribution), then:
//   row_scan:  inclusive scan along y (contiguous dim) per x-row
//   col_scan:  PARALLEL block scan along x per y-column + finalize max(|h|,|v|)
// Scale 1/(bin_area*CAP) folded into per-net weights.

#define NBX 512
#define NBY 512
#define DPITCH 514          // row pitch of diff arrays (need columns 0..512)
#define DROWS  513          // need rows 0..512

__device__ float g_diffH[DROWS * DPITCH];
__device__ float g_diffV[DROWS * DPITCH];

__device__ __forceinline__ float edge(int i, float bs) {
    return (float)i * bs;   // bs = 1000/512 = 125/64 exact; i*bs exact here
}

// overlap of [vmin, vmax] with bin i, clipped to [0, bs] — identical formula
// to the reference's clip(min(vmax, e[i+1]) - max(vmin, e[i]), 0, bs).
__device__ __forceinline__ float fval(float vmin, float vmax, int i, float bs) {
    float lo_e = edge(i, bs);
    float hi_e = edge(i + 1, bs);
    float ov = fminf(vmax, hi_e) - fmaxf(vmin, lo_e);
    return fminf(fmaxf(ov, 0.0f), bs);
}

// exact bin index of v (0..nb-1), correcting fp error in the division against
// the exactly-representable edges.
__device__ __forceinline__ int bin_of(float v, float inv_bs, float bs, int nb) {
    int i = (int)(v * inv_bs);
    if (i > nb - 1) i = nb - 1;
    if (i < 0) i = 0;
    if (i > 0 && v < edge(i, bs)) --i;
    else if (i < nb - 1 && v >= edge(i + 1, bs)) ++i;
    return i;
}

__global__ void zero_diff_kernel() {
    int total = DROWS * DPITCH;
    for (int i = blockIdx.x * blockDim.x + threadIdx.x; i < total;
         i += gridDim.x * blockDim.x) {
        g_diffH[i] = 0.0f;
        g_diffV[i] = 0.0f;
    }
}

__global__ void scatter_kernel(const float* __restrict__ pin_pos,
                               const float* __restrict__ net_weights,
                               const int* __restrict__ netpin_start,
                               const int* __restrict__ flat_netpin,
                               int num_nets, int P) {
    const float BSX = 1.953125f;          // 1000/512, exact
    const float BSY = 1.953125f;
    const float INV_BSX = 1.0f / 1.953125f;
    const float INV_BSY = 1.0f / 1.953125f;
    const float SCALE = 262144.0f / 100000.0f;  // 1/(BSX*BSY*0.1)

    for (int n = blockIdx.x * blockDim.x + threadIdx.x; n < num_nets;
         n += gridDim.x * blockDim.x) {
        int s = netpin_start[n];
        int e = netpin_start[n + 1];

        float xmin = 3.0e38f, xmax = -3.0e38f, ymin = 3.0e38f, ymax = -3.0e38f;
        for (int p = s; p < e; ++p) {
            int idx = __ldg(&flat_netpin[p]);
            float x = __ldg(&pin_pos[idx]);
            float y = __ldg(&pin_pos[P + idx]);
            xmin = fminf(xmin, x); xmax = fmaxf(xmax, x);
            ymin = fminf(ymin, y); ymax = fmaxf(ymax, y);
        }

        float sx = xmax - xmin;
        float sy = ymax - ymin;
        // zero span in either dim zeroes the ox*oy product for BOTH maps
        if (!(sx > 0.0f) || !(sy > 0.0f)) continue;

        float wt = net_weights[n] * SCALE;
        float wh = wt / sy;   // horizontal demand weight
        float wv = wt / sx;   // vertical demand weight

        int lox = bin_of(xmin, INV_BSX, BSX, NBX);
        int hix = bin_of(xmax, INV_BSX, BSX, NBX);
        int loy = bin_of(ymin, INV_BSY, BSY, NBY);
        int hiy = bin_of(ymax, INV_BSY, BSY, NBY);

        // unique difference positions along x: subset of {lo, lo+1, hi, hi+1}
        int pxs[4]; float dxs[4]; int mx = 0;
        pxs[mx++] = lox;
        pxs[mx++] = lox + 1;
        if (hix > lox + 1) pxs[mx++] = hix;
        if (hix + 1 > lox + 1) pxs[mx++] = hix + 1;
#pragma unroll
        for (int i = 0; i < 4; ++i) {
            if (i < mx)
                dxs[i] = fval(xmin, xmax, pxs[i], BSX)
                       - fval(xmin, xmax, pxs[i] - 1, BSX);
        }

        int pys[4]; float dys[4]; int my = 0;
        pys[my++] = loy;
        pys[my++] = loy + 1;
        if (hiy > loy + 1) pys[my++] = hiy;
        if (hiy + 1 > loy + 1) pys[my++] = hiy + 1;
#pragma unroll
        for (int j = 0; j < 4; ++j) {
            if (j < my)
                dys[j] = fval(ymin, ymax, pys[j], BSY)
                       - fval(ymin, ymax, pys[j] - 1, BSY);
        }

#pragma unroll
        for (int i = 0; i < 4; ++i) {
            if (i >= mx) break;
#pragma unroll
            for (int j = 0; j < 4; ++j) {
                if (j >= my) break;
                float v = dxs[i] * dys[j];
                int off = pxs[i] * DPITCH + pys[j];
                atomicAdd(&g_diffH[off], wh * v);
                atomicAdd(&g_diffV[off], wv * v);
            }
        }
    }
}

// inclusive scan along y (contiguous dim) for rows 0..511 of each diff array.
__global__ void row_scan_kernel() {
    __shared__ float warp_sums[16];
    float* D = blockIdx.y ? g_diffV : g_diffH;
    int row = blockIdx.x;
    int t = threadIdx.x;
    int lane = t & 31, wid = t >> 5;

    float v = D[row * DPITCH + t];
#pragma unroll
    for (int o = 1; o < 32; o <<= 1) {
        float nv = __shfl_up_sync(0xffffffff, v, o);
        if (lane >= o) v += nv;
    }
    if (lane == 31) warp_sums[wid] = v;
    __syncthreads();
    if (wid == 0) {
        float sv = (lane < 16) ? warp_sums[lane] : 0.0f;
#pragma unroll
        for (int o = 1; o < 16; o <<= 1) {
            float nv = __shfl_up_sync(0xffffffff, sv, o);
            if (lane >= o) sv += nv;
        }
        if (lane < 16) warp_sums[lane] = sv;
    }
    __syncthreads();
    if (wid > 0) v += warp_sums[wid - 1];
    D[row * DPITCH + t] = v;
}

// PARALLEL inclusive scan along x for one y-column per block (both maps at
// once), then finalize out = max(|h|,|v|).  512 blocks x 512 threads.
__global__ void col_scan_finalize_kernel(float* __restrict__ out) {
    __shared__ float wsH[16];
    __shared__ float wsV[16];
    int y = blockIdx.x;          // column
    int t = threadIdx.x;         // x index
    int lane = t & 31, wid = t >> 5;

    float h = g_diffH[t * DPITCH + y];
    float v = g_diffV[t * DPITCH + y];

    // warp-level inclusive scans (both maps in the same shuffle sequence)
#pragma unroll
    for (int o = 1; o < 32; o <<= 1) {
        float nh = __shfl_up_sync(0xffffffff, h, o);
        float nv = __shfl_up_sync(0xffffffff, v, o);
        if (lane >= o) { h += nh; v += nv; }
    }
    if (lane == 31) { wsH[wid] = h; wsV[wid] = v; }
    __syncthreads();

    // scan the 16 warp sums of BOTH maps in warp 0 using width-16 segments:
    // lanes 0..15 -> H sums, lanes 16..31 -> V sums.
    if (wid == 0) {
        float sv = (lane < 16) ? wsH[lane] : wsV[lane - 16];
#pragma unroll
        for (int o = 1; o < 16; o <<= 1) {
            float nv = __shfl_up_sync(0xffffffff, sv, o, 16);
            if ((lane & 15) >= o) sv += nv;
        }
        if (lane < 16) wsH[lane] = sv; else wsV[lane - 16] = sv;
    }
    __syncthreads();

    if (wid > 0) { h += wsH[wid - 1]; v += wsV[wid - 1]; }
    out[t * NBY + y] = fmaxf(fabsf(h), fabsf(v));
}

extern "C" void kernel_launch(void* const* d_in, const int* in_sizes, int n_in,
                              void* d_out, int out_size) {
    const float* pin_pos      = (const float*)d_in[0];
    const float* net_weights  = (const float*)d_in[1];
    const int*   netpin_start = (const int*)d_in[2];
    const int*   flat_netpin  = (const int*)d_in[3];
    float* out = (float*)d_out;

    int P = in_sizes[0] / 2;
    int num_nets = in_sizes[2] - 1;

    zero_diff_kernel<<<256, 256>>>();
    scatter_kernel<<<(num_nets + 127) / 128, 128>>>(
        pin_pos, net_weights, netpin_start, flat_netpin, num_nets, P);
    row_scan_kernel<<<dim3(NBX, 2), NBY>>>();
    col_scan_finalize_kernel<<<NBY, NBX>>>(out);
}